// round 11
// baseline (speedup 1.0000x reference)
#include <cuda_runtime.h>

#define TT    512
#define HH    50
#define KREG  34
#define KTAIL (HH - KREG)   // 16

typedef unsigned long long u64;

__device__ __forceinline__ u64 pack2(float x) {
    u64 r; asm("mov.b64 %0, {%1,%1};" : "=l"(r) : "f"(x)); return r;
}
__device__ __forceinline__ u64 fma2(u64 a, u64 b, u64 c) {
    u64 d; asm("fma.rn.f32x2 %0, %1, %2, %3;" : "=l"(d) : "l"(a), "l"(b), "l"(c)); return d;
}
__device__ __forceinline__ void unpk(u64 v, float& lo, float& hi) {
    asm("mov.b64 {%0, %1}, %2;" : "=f"(lo), "=f"(hi) : "l"(v));
}
__device__ __forceinline__ u64 bfly64(u64 v, unsigned m) {
    unsigned lo, hi;
    asm("mov.b64 {%0, %1}, %2;" : "=r"(lo), "=r"(hi) : "l"(v));
    lo = __shfl_xor_sync(m, lo, 1);
    hi = __shfl_xor_sync(m, hi, 1);
    u64 r; asm("mov.b64 %0, {%1, %2};" : "=l"(r) : "r"(lo), "r"(hi));
    return r;
}
__device__ __forceinline__ float tanhap(float x) {
    float y; asm("tanh.approx.f32 %0, %1;" : "=f"(y) : "f"(x)); return y;
}
__device__ __forceinline__ float sigap(float x) {
    return fmaf(tanhap(0.5f * x), 0.5f, 0.5f);
}

#define NBAR(id) asm volatile("bar.sync %0, 128;" :: "r"(id) : "memory")

// One warp-group (128 threads) = independent LSTM over NB=2*NP batches,
// synchronized only by named barrier BID. x staged in 64-step chunks (xc),
// W_hh tail (k>=KREG) read from the shared lane-coalesced table wt.
template<int NP, int BID>
__device__ __forceinline__ void run_group(
    float* xc, float* hb, const float* wt, float* sink, int b0, int tid,
    int stagger_iters,
    const float* __restrict__ x,    const float* __restrict__ W_ih,
    const float* __restrict__ W_hh, const float* __restrict__ b_ih,
    const float* __restrict__ b_hh, const float* __restrict__ fc_w,
    const float* __restrict__ fc_b, float* __restrict__ out)
{
    constexpr int NB = 2 * NP;   // batches; h row width = NB floats

    for (int i = tid; i < 2 * HH * NB; i += 128) hb[i] = 0.f;

    // row mapping: even tid=2j -> rows (j: i-gate, j+100: g-gate)
    //              odd  tid=2j+1 -> rows (j+50: f-gate, j+150: o-gate)
    const bool act = (tid < 2 * HH);
    const int  j   = tid >> 1;
    const int  r0  = (tid & 1) ? (j + HH) : j;
    const int  r1  = r0 + 2 * HH;

    float w0[KREG], w1[KREG];
    u64 wx0 = 0, wx1 = 0, bi0 = 0, bi1 = 0;
    if (act) {
        #pragma unroll
        for (int k = 0; k < KREG; k++) {
            w0[k] = W_hh[r0 * HH + k];
            w1[k] = W_hh[r1 * HH + k];
        }
        wx0 = pack2(W_ih[r0]);
        wx1 = pack2(W_ih[r1]);
        bi0 = pack2(b_ih[r0] + b_hh[r0]);
        bi1 = pack2(b_ih[r1] + b_hh[r1]);
    }
    float c0 = 0.f, c1 = 0.f;

    // anti-phase stagger (dependent-FMA delay)
    if (stagger_iters) {
        float d = b_hh[0];
        #pragma unroll 1
        for (int i = 0; i < stagger_iters; i++) d = fmaf(d, 1.0000001f, 1e-7f);
        if (d == -1e30f) *sink = d;   // never true; defeats DCE only
    }

    const float4* xg = reinterpret_cast<const float4*>(x);

    #pragma unroll 1
    for (int ch = 0; ch < TT / 64; ch++) {
        // ---- refill x chunk: 64 timesteps x NB batches ----
        for (int idx = tid; idx < NB * 16; idx += 128) {
            int bb = idx >> 4, t4 = idx & 15;
            float4 v = xg[(size_t)(b0 + bb) * 128 + ch * 16 + t4];
            int tt = t4 * 4;
            xc[(tt + 0) * NB + bb] = v.x; xc[(tt + 1) * NB + bb] = v.y;
            xc[(tt + 2) * NB + bb] = v.z; xc[(tt + 3) * NB + bb] = v.w;
        }
        NBAR(BID);

        #pragma unroll 1
        for (int tt = 0; tt < 64; tt++) {
            const int t = ch * 64 + tt;
            if (act) {
                const float* hs = hb + (t & 1) * HH * NB;
                unsigned m = __activemask();
                bool ev = !(tid & 1);

                if (NP == 2) {
                    u64 A00, A01, A10, A11;
                    {
                        ulonglong2 q = *reinterpret_cast<const ulonglong2*>(&xc[tt * 4]);
                        A00 = fma2(q.x, wx0, bi0); A01 = fma2(q.y, wx0, bi0);
                        A10 = fma2(q.x, wx1, bi1); A11 = fma2(q.y, wx1, bi1);
                    }
                    #pragma unroll
                    for (int k = 0; k < KREG; k++) {
                        u64 w0p = pack2(w0[k]);
                        u64 w1p = pack2(w1[k]);
                        ulonglong2 q = *reinterpret_cast<const ulonglong2*>(hs + k * 4);
                        A00 = fma2(q.x, w0p, A00); A01 = fma2(q.y, w0p, A01);
                        A10 = fma2(q.x, w1p, A10); A11 = fma2(q.y, w1p, A11);
                    }
                    #pragma unroll
                    for (int kt = 0; kt < KTAIL; kt++) {
                        u64 w0p = pack2(wt[(kt * 2 + 0) * 128 + tid]);
                        u64 w1p = pack2(wt[(kt * 2 + 1) * 128 + tid]);
                        ulonglong2 q = *reinterpret_cast<const ulonglong2*>(hs + (KREG + kt) * 4);
                        A00 = fma2(q.x, w0p, A00); A01 = fma2(q.y, w0p, A01);
                        A10 = fma2(q.x, w1p, A10); A11 = fma2(q.y, w1p, A11);
                    }

                    // exchange: even keeps batches 0,1; odd keeps 2,3
                    u64 s0 = bfly64(ev ? A01 : A00, m);
                    u64 s1 = bfly64(ev ? A11 : A10, m);
                    u64 GI = ev ? A00 : s0;
                    u64 GG = ev ? A10 : s1;
                    u64 GF = ev ? s0 : A01;
                    u64 GO = ev ? s1 : A11;
                    float i0, i1, g0, g1, f0, f1, o0, o1;
                    unpk(GI, i0, i1); unpk(GG, g0, g1);
                    unpk(GF, f0, f1); unpk(GO, o0, o1);
                    c0 = sigap(f0) * c0 + sigap(i0) * tanhap(g0);
                    c1 = sigap(f1) * c1 + sigap(i1) * tanhap(g1);
                    float2 hn = make_float2(sigap(o0) * tanhap(c0),
                                            sigap(o1) * tanhap(c1));
                    *reinterpret_cast<float2*>(
                        hb + ((t + 1) & 1) * HH * 4 + j * 4 + (ev ? 0 : 2)) = hn;
                } else {
                    // NP==1: 2 batches, even lane -> batch 0, odd -> batch 1
                    u64 A0, A1;
                    {
                        u64 q = *reinterpret_cast<const u64*>(&xc[tt * 2]);
                        A0 = fma2(q, wx0, bi0);
                        A1 = fma2(q, wx1, bi1);
                    }
                    #pragma unroll
                    for (int k = 0; k < KREG; k++) {
                        u64 q = *reinterpret_cast<const u64*>(hs + k * 2);
                        A0 = fma2(q, pack2(w0[k]), A0);
                        A1 = fma2(q, pack2(w1[k]), A1);
                    }
                    #pragma unroll
                    for (int kt = 0; kt < KTAIL; kt++) {
                        u64 q = *reinterpret_cast<const u64*>(hs + (KREG + kt) * 2);
                        A0 = fma2(q, pack2(wt[(kt * 2 + 0) * 128 + tid]), A0);
                        A1 = fma2(q, pack2(wt[(kt * 2 + 1) * 128 + tid]), A1);
                    }
                    u64 s0 = bfly64(A0, m);   // even rx (f b0,b1) / odd rx (i b0,b1)
                    u64 s1 = bfly64(A1, m);   // even rx (o b0,b1) / odd rx (g b0,b1)
                    float iv, gv, fv, ov, d0;
                    if (ev) { unpk(A0, iv, d0); unpk(A1, gv, d0);
                              unpk(s0, fv, d0); unpk(s1, ov, d0); }
                    else    { unpk(s0, d0, iv); unpk(s1, d0, gv);
                              unpk(A0, d0, fv); unpk(A1, d0, ov); }
                    c0 = sigap(fv) * c0 + sigap(iv) * tanhap(gv);
                    hb[((t + 1) & 1) * HH * 2 + j * 2 + (ev ? 0 : 1)]
                        = sigap(ov) * tanhap(c0);
                }
            }
            NBAR(BID);
        }
    }

    // ===== final FC on h_T (buffer 0 since TT is even) =====
    if (tid < NB * 3) {
        int bb = tid / 3, o = tid % 3;
        float s = fc_b[o];
        #pragma unroll
        for (int k = 0; k < HH; k++) s += hb[k * NB + bb] * fc_w[o * HH + k];
        out[(size_t)(b0 + bb) * 3 + o] = s;
    }
}

__global__ void __launch_bounds__(512, 1)
lstm_fused(const float* __restrict__ x,    const float* __restrict__ W_ih,
           const float* __restrict__ W_hh, const float* __restrict__ b_ih,
           const float* __restrict__ b_hh, const float* __restrict__ fc_w,
           const float* __restrict__ fc_b, float* __restrict__ out)
{
    __shared__ __align__(16) float xcA[64 * 4], xcB[64 * 4], xcC[64 * 4];
    __shared__ __align__(16) float xcD[64 * 2];
    __shared__ __align__(16) float hA[2 * HH * 4], hB[2 * HH * 4], hC[2 * HH * 4];
    __shared__ __align__(16) float hD[2 * HH * 2];
    __shared__ __align__(16) float wt[KTAIL * 2 * 128];   // 16 KB
    __shared__ float sink;

    const int tid = threadIdx.x;

    // W_hh tail table, lane-coalesced by local tid (same mapping all groups)
    if (tid < 2 * HH) {
        int jj = tid >> 1;
        int rr0 = (tid & 1) ? (jj + HH) : jj;
        int rr1 = rr0 + 2 * HH;
        #pragma unroll
        for (int kt = 0; kt < KTAIL; kt++) {
            wt[(kt * 2 + 0) * 128 + tid] = W_hh[rr0 * HH + KREG + kt];
            wt[(kt * 2 + 1) * 128 + tid] = W_hh[rr1 * HH + KREG + kt];
        }
    }
    __syncthreads();

    // 14 batches per block = 4+4+4+2 over four independent warp-groups,
    // one block per SM (grid 147). Capped b0 -> tail batches recomputed
    // identically by two blocks (benign duplicate writes).
    const int b0 = min((int)blockIdx.x * 14, 2048 - 14);

    if (tid < 128) {
        run_group<2, 1>(xcA, hA, wt, &sink, b0, tid, 0,
                        x, W_ih, W_hh, b_ih, b_hh, fc_w, fc_b, out);
    } else if (tid < 256) {
        run_group<2, 2>(xcB, hB, wt, &sink, b0 + 4, tid - 128, 110,
                        x, W_ih, W_hh, b_ih, b_hh, fc_w, fc_b, out);
    } else if (tid < 384) {
        run_group<2, 3>(xcC, hC, wt, &sink, b0 + 8, tid - 256, 220,
                        x, W_ih, W_hh, b_ih, b_hh, fc_w, fc_b, out);
    } else {
        run_group<1, 4>(xcD, hD, wt, &sink, b0 + 12, tid - 384, 330,
                        x, W_ih, W_hh, b_ih, b_hh, fc_w, fc_b, out);
    }
}

extern "C" void kernel_launch(void* const* d_in, const int* in_sizes, int n_in,
                              void* d_out, int out_size) {
    const float* x    = (const float*)d_in[0];
    const float* W_ih = (const float*)d_in[1];
    const float* W_hh = (const float*)d_in[2];
    const float* b_ih = (const float*)d_in[3];
    const float* b_hh = (const float*)d_in[4];
    const float* fc_w = (const float*)d_in[5];
    const float* fc_b = (const float*)d_in[6];
    lstm_fused<<<147, 512>>>(x, W_ih, W_hh, b_ih, b_hh, fc_w, fc_b, (float*)d_out);
}

// round 13
// speedup vs baseline: 1.2681x; 1.2681x over previous
#include <cuda_runtime.h>
#include <cuda_bf16.h>

#define TT   512
#define HH   50
#define NTH  256
#define NBAT 16
#define KT   10          // k16 tiles: K=160 = [Whi(50) | Whi(50) | Wlo(50) | pad]
#define HTP  200         // bf16 per hT row = 400B = 100 words (100%32=4 -> conflict-free)
#define GTP  204         // f32 per gT row (204%32=12 -> conflict-free STS pattern)

typedef unsigned int u32;

__device__ __forceinline__ float tanhap(float x) {
    float y; asm("tanh.approx.f32 %0, %1;" : "=f"(y) : "f"(x)); return y;
}
__device__ __forceinline__ float sigap(float x) {
    return fmaf(tanhap(0.5f * x), 0.5f, 0.5f);
}
__device__ __forceinline__ u32 pkbf(float a, float b) {
    u32 lo = (u32)__bfloat16_as_ushort(__float2bfloat16(a));
    u32 hi = (u32)__bfloat16_as_ushort(__float2bfloat16(b));
    return (hi << 16) | lo;
}
__device__ __forceinline__ void mma16816(float* d, const u32* a, u32 b0, u32 b1) {
    asm volatile(
        "mma.sync.aligned.m16n8k16.row.col.f32.bf16.bf16.f32 "
        "{%0,%1,%2,%3}, {%4,%5,%6,%7}, {%8,%9}, {%0,%1,%2,%3};"
        : "+f"(d[0]), "+f"(d[1]), "+f"(d[2]), "+f"(d[3])
        : "r"(a[0]), "r"(a[1]), "r"(a[2]), "r"(a[3]), "r"(b0), "r"(b1));
}

// A-operand element W'(r,k): k<50 -> bf16(W); 50..99 -> bf16(W) (dup for h_lo);
// 100..149 -> bf16(W - bf16(W)); else 0. Rows >=200 zero.
__device__ __forceinline__ float wprime(const float* W, int r, int k) {
    if (r >= 200 || k >= 150) return 0.f;
    int kk = (k < 50) ? k : (k < 100 ? k - 50 : k - 100);
    float w = W[r * HH + kk];
    if (k < 100) return w;                     // bf16 rounding happens in pkbf
    float hi = __bfloat162float(__float2bfloat16(w));
    return w - hi;                             // lo residual
}

__global__ void __launch_bounds__(NTH, 1)
lstm_mma(const float* __restrict__ x,    const float* __restrict__ W_ih,
         const float* __restrict__ W_hh, const float* __restrict__ b_ih,
         const float* __restrict__ b_hh, const float* __restrict__ fc_w,
         const float* __restrict__ fc_b, float* __restrict__ out)
{
    // hT[buf][n][k]: h operand, bf16, k-major, double buffered
    __shared__ __align__(16) __nv_bfloat16 hT[2][NBAT][HTP];   // 12.8 KB
    __shared__ __align__(16) float gT[NBAT][GTP];              // 13.1 KB (n-major gates)
    __shared__ __align__(16) float x_sm[64][NBAT];             // 4 KB chunked x

    const int tid = threadIdx.x;
    const int wid = tid >> 5;
    const int lan = tid & 31;
    const int g   = lan >> 2;       // mma group id
    const int tg  = lan & 3;        // thread-in-group
    const int b0  = (int)blockIdx.x * NBAT;

    // ---- zero hT (h=0 at t=0) ----
    for (int i = tid; i < 2 * NBAT * HTP / 2; i += NTH)
        reinterpret_cast<u32*>(&hT[0][0][0])[i] = 0;

    // ---- A fragments in registers, persistent across all 512 steps ----
    // warps 0-6: m-tiles 2w, 2w+1 (rows 32w .. 32w+31)
    u32 A[2][KT][4];
    const bool mmaw = (wid < 7);
    if (mmaw) {
        #pragma unroll
        for (int mi = 0; mi < 2; mi++) {
            int r_lo = (2 * wid + mi) * 16 + g;
            #pragma unroll
            for (int kt = 0; kt < KT; kt++) {
                int ka = kt * 16 + 2 * tg;
                A[mi][kt][0] = pkbf(wprime(W_hh, r_lo,     ka),     wprime(W_hh, r_lo,     ka + 1));
                A[mi][kt][1] = pkbf(wprime(W_hh, r_lo + 8, ka),     wprime(W_hh, r_lo + 8, ka + 1));
                A[mi][kt][2] = pkbf(wprime(W_hh, r_lo,     ka + 8), wprime(W_hh, r_lo,     ka + 9));
                A[mi][kt][3] = pkbf(wprime(W_hh, r_lo + 8, ka + 8), wprime(W_hh, r_lo + 8, ka + 9));
            }
        }
    }

    // ---- update-thread constants: thread t<200 -> unit j, batches 4q..4q+3 ----
    const bool upd = (tid < 200);
    const int  j   = tid % HH;
    const int  q   = tid / HH;       // 0..3
    float wxi = 0.f, wxf = 0.f, wxg = 0.f, wxo = 0.f;
    float bii = 0.f, bif = 0.f, big = 0.f, bio = 0.f;
    if (upd) {
        wxi = W_ih[j];          bii = b_ih[j]          + b_hh[j];
        wxf = W_ih[j + HH];     bif = b_ih[j + HH]     + b_hh[j + HH];
        wxg = W_ih[j + 2*HH];   big = b_ih[j + 2*HH]   + b_hh[j + 2*HH];
        wxo = W_ih[j + 3*HH];   bio = b_ih[j + 3*HH]   + b_hh[j + 3*HH];
    }
    float cc[4] = {0.f, 0.f, 0.f, 0.f};
    float hh[4] = {0.f, 0.f, 0.f, 0.f};

    __syncthreads();

    // ================= recurrence =================
    #pragma unroll 1
    for (int t = 0; t < TT; t++) {
        const int tt = t & 63;
        if (tt == 0) {
            // refill x chunk: 16 batches x 16 float4 = 256 loads, one per thread
            int bb = tid >> 4, qq = tid & 15;
            float4 v = reinterpret_cast<const float4*>(x)
                           [(size_t)(b0 + bb) * 128 + (t >> 6) * 16 + qq];
            x_sm[qq * 4 + 0][bb] = v.x; x_sm[qq * 4 + 1][bb] = v.y;
            x_sm[qq * 4 + 2][bb] = v.z; x_sm[qq * 4 + 3][bb] = v.w;
        }

        // ---- GEMM: D[200x16] = A @ hT[t&1] ----
        if (mmaw) {
            const __nv_bfloat16 (*hb)[HTP] = hT[t & 1];
            float d[2][2][4];
            #pragma unroll
            for (int mi = 0; mi < 2; mi++)
                #pragma unroll
                for (int nf = 0; nf < 2; nf++)
                    #pragma unroll
                    for (int e = 0; e < 4; e++) d[mi][nf][e] = 0.f;

            #pragma unroll
            for (int kt = 0; kt < KT; kt++) {
                int kof = kt * 16 + 2 * tg;
                u32 b00 = *reinterpret_cast<const u32*>(&hb[g    ][kof]);
                u32 b01 = *reinterpret_cast<const u32*>(&hb[g    ][kof + 8]);
                u32 b10 = *reinterpret_cast<const u32*>(&hb[g + 8][kof]);
                u32 b11 = *reinterpret_cast<const u32*>(&hb[g + 8][kof + 8]);
                mma16816(d[0][0], A[0][kt], b00, b01);
                mma16816(d[1][0], A[1][kt], b00, b01);
                mma16816(d[0][1], A[0][kt], b10, b11);
                mma16816(d[1][1], A[1][kt], b10, b11);
            }

            // D -> gT (transposed, n-major): conflict-free by GTP%32==12
            #pragma unroll
            for (int mi = 0; mi < 2; mi++) {
                int r_lo = (2 * wid + mi) * 16 + g;
                int r_hi = r_lo + 8;
                #pragma unroll
                for (int nf = 0; nf < 2; nf++) {
                    int n = nf * 8 + 2 * tg;
                    if (r_lo < 200) {
                        gT[n][r_lo]     = d[mi][nf][0];
                        gT[n + 1][r_lo] = d[mi][nf][1];
                    }
                    if (r_hi < 200) {
                        gT[n][r_hi]     = d[mi][nf][2];
                        gT[n + 1][r_hi] = d[mi][nf][3];
                    }
                }
            }
        }
        __syncthreads();     // gates + x ready

        // ---- cell update: 4 cells/thread; write h hi/lo bf16 into hT[next] ----
        if (upd) {
            __nv_bfloat16 (*hw)[HTP] = hT[(t + 1) & 1];
            #pragma unroll
            for (int m = 0; m < 4; m++) {
                int n = q * 4 + m;
                float xv = x_sm[tt][n];
                float I = gT[n][j]          + fmaf(wxi, xv, bii);
                float F = gT[n][j + HH]     + fmaf(wxf, xv, bif);
                float G = gT[n][j + 2*HH]   + fmaf(wxg, xv, big);
                float O = gT[n][j + 3*HH]   + fmaf(wxo, xv, bio);
                cc[m] = sigap(F) * cc[m] + sigap(I) * tanhap(G);
                hh[m] = sigap(O) * tanhap(cc[m]);
                __nv_bfloat16 hi = __float2bfloat16(hh[m]);
                float lo = hh[m] - __bfloat162float(hi);
                hw[n][j]          = hi;
                hw[n][j + HH]     = __float2bfloat16(lo);
                hw[n][j + 2 * HH] = hi;
            }
        }
        __syncthreads();     // hT[next] ready; gT free for rewrite
    }

    // ================= FC epilogue on h_T =================
    if (upd) {
        #pragma unroll
        for (int m = 0; m < 4; m++) gT[q * 4 + m][j] = hh[m];
    }
    __syncthreads();
    if (tid < NBAT * 3) {
        int bb = tid / 3, o = tid % 3;
        float s = fc_b[o];
        #pragma unroll
        for (int k = 0; k < HH; k++) s += gT[bb][k] * fc_w[o * HH + k];
        out[(size_t)(b0 + bb) * 3 + o] = s;
    }
}

extern "C" void kernel_launch(void* const* d_in, const int* in_sizes, int n_in,
                              void* d_out, int out_size) {
    const float* x    = (const float*)d_in[0];
    const float* W_ih = (const float*)d_in[1];
    const float* W_hh = (const float*)d_in[2];
    const float* b_ih = (const float*)d_in[3];
    const float* b_hh = (const float*)d_in[4];
    const float* fc_w = (const float*)d_in[5];
    const float* fc_b = (const float*)d_in[6];
    lstm_mma<<<2048 / NBAT, NTH>>>(x, W_ih, W_hh, b_ih, b_hh, fc_w, fc_b, (float*)d_out);
}

// round 14
// speedup vs baseline: 1.4422x; 1.1373x over previous
#include <cuda_runtime.h>
#include <cuda_bf16.h>

#define TT   512
#define HH   50
#define NTH  448         // 2 groups x 224 (7 warps each)
#define NBAT 16          // per block; 8 per group
#define NG   8           // batches per group
#define KT   10          // k16 tiles: K=160 = [Whi(50) | Whi(50) | Wlo(50) | pad]
#define HTP  200         // bf16 per hT row (400B; 100 words, %32=4 -> staggered banks)
#define GTP  204         // f32 per gT row (%32=12 -> conflict-free STS)

typedef unsigned int u32;

__device__ __forceinline__ float tanhap(float x) {
    float y; asm("tanh.approx.f32 %0, %1;" : "=f"(y) : "f"(x)); return y;
}
__device__ __forceinline__ float sigap(float x) {
    return fmaf(tanhap(0.5f * x), 0.5f, 0.5f);
}
__device__ __forceinline__ u32 pkbf(float a, float b) {
    u32 lo = (u32)__bfloat16_as_ushort(__float2bfloat16(a));
    u32 hi = (u32)__bfloat16_as_ushort(__float2bfloat16(b));
    return (hi << 16) | lo;
}
__device__ __forceinline__ void mma16816(float* d, const u32* a, u32 b0, u32 b1) {
    asm volatile(
        "mma.sync.aligned.m16n8k16.row.col.f32.bf16.bf16.f32 "
        "{%0,%1,%2,%3}, {%4,%5,%6,%7}, {%8,%9}, {%0,%1,%2,%3};"
        : "+f"(d[0]), "+f"(d[1]), "+f"(d[2]), "+f"(d[3])
        : "r"(a[0]), "r"(a[1]), "r"(a[2]), "r"(a[3]), "r"(b0), "r"(b1));
}

#define NBAR(id) asm volatile("bar.sync %0, 224;" :: "r"(id) : "memory")

// A element W'(r,k): k<50 -> W (for h_hi); 50..99 -> W (for h_lo);
// 100..149 -> W - bf16(W) (residual, for h_hi); else 0. Rows >=200 zero.
__device__ __forceinline__ float wprime(const float* W, int r, int k) {
    if (r >= 200 || k >= 150) return 0.f;
    int kk = (k < 50) ? k : (k < 100 ? k - 50 : k - 100);
    float w = W[r * HH + kk];
    if (k < 100) return w;
    float hi = __bfloat162float(__float2bfloat16(w));
    return w - hi;
}

__global__ void __launch_bounds__(NTH, 1)
lstm_mma(const float* __restrict__ x,    const float* __restrict__ W_ih,
         const float* __restrict__ W_hh, const float* __restrict__ b_ih,
         const float* __restrict__ b_hh, const float* __restrict__ fc_w,
         const float* __restrict__ fc_b, float* __restrict__ out)
{
    // per-group buffers
    __shared__ __align__(16) __nv_bfloat16 hT[2][2][NG][HTP];  // [grp][buf][n][k] 12.8 KB
    __shared__ __align__(16) float gT[2][NG][GTP];             // [grp][n][r]     13.1 KB
    __shared__ __align__(16) float x_sm[2][64][NG];            // [grp][t][n]      4 KB
    __shared__ float sink;

    const int tid  = threadIdx.x;
    const int grp  = (tid < 224) ? 0 : 1;
    const int ltid = tid - grp * 224;
    const int lwid = ltid >> 5;          // 0..6
    const int lan  = ltid & 31;
    const int g    = lan >> 2;
    const int tg   = lan & 3;
    const int b0g  = (int)blockIdx.x * NBAT + grp * NG;

    // ---- zero hT (h=0 at t=0) ----
    for (int i = tid; i < 2 * 2 * NG * HTP / 2; i += NTH)
        reinterpret_cast<u32*>(&hT[0][0][0][0])[i] = 0;

    // ---- A fragments in registers, persistent; warp w -> m-tiles 2w,2w+1 ----
    u32 A[2][KT][4];
    {
        #pragma unroll
        for (int mi = 0; mi < 2; mi++) {
            int r_lo = (2 * lwid + mi) * 16 + g;
            #pragma unroll
            for (int kt = 0; kt < KT; kt++) {
                int ka = kt * 16 + 2 * tg;
                A[mi][kt][0] = pkbf(wprime(W_hh, r_lo,     ka),     wprime(W_hh, r_lo,     ka + 1));
                A[mi][kt][1] = pkbf(wprime(W_hh, r_lo + 8, ka),     wprime(W_hh, r_lo + 8, ka + 1));
                A[mi][kt][2] = pkbf(wprime(W_hh, r_lo,     ka + 8), wprime(W_hh, r_lo,     ka + 9));
                A[mi][kt][3] = pkbf(wprime(W_hh, r_lo + 8, ka + 8), wprime(W_hh, r_lo + 8, ka + 9));
            }
        }
    }

    // ---- update constants: ltid<200 -> unit j, batches 2q, 2q+1 ----
    const bool upd = (ltid < 200);
    const int  j   = ltid % HH;
    const int  q   = ltid / HH;          // 0..3
    float wxi = 0.f, wxf = 0.f, wxg = 0.f, wxo = 0.f;
    float bii = 0.f, bif = 0.f, big = 0.f, bio = 0.f;
    if (upd) {
        wxi = W_ih[j];          bii = b_ih[j]          + b_hh[j];
        wxf = W_ih[j + HH];     bif = b_ih[j + HH]     + b_hh[j + HH];
        wxg = W_ih[j + 2*HH];   big = b_ih[j + 2*HH]   + b_hh[j + 2*HH];
        wxo = W_ih[j + 3*HH];   bio = b_ih[j + 3*HH]   + b_hh[j + 3*HH];
    }
    float cc[2] = {0.f, 0.f}, hh[2] = {0.f, 0.f};

    __syncthreads();   // all shared init done before groups diverge

    // ---- anti-phase stagger for group 1 (~700 cyc dependent-FMA delay) ----
    if (grp == 1) {
        float d = b_hh[0];
        #pragma unroll 1
        for (int i = 0; i < 175; i++) d = fmaf(d, 1.0000001f, 1e-7f);
        if (d == -1e30f) sink = d;   // never true; defeats DCE
    }

    // ================= recurrence =================
    #pragma unroll 1
    for (int t = 0; t < TT; t++) {
        const int tt = t & 63;
        if (tt == 0) {
            // refill x chunk: 8 batches x 16 float4 = 128 loads
            if (ltid < 128) {
                int bb = ltid >> 4, qq = ltid & 15;
                float4 v = reinterpret_cast<const float4*>(x)
                               [(size_t)(b0g + bb) * 128 + (t >> 6) * 16 + qq];
                x_sm[grp][qq * 4 + 0][bb] = v.x; x_sm[grp][qq * 4 + 1][bb] = v.y;
                x_sm[grp][qq * 4 + 2][bb] = v.z; x_sm[grp][qq * 4 + 3][bb] = v.w;
            }
            NBAR(1 + grp);
        }

        // ---- GEMM: D[200x8] = A @ hT[grp][t&1] ----
        {
            const __nv_bfloat16 (*hb)[HTP] = hT[grp][t & 1];
            float d0[4] = {0.f, 0.f, 0.f, 0.f};
            float d1[4] = {0.f, 0.f, 0.f, 0.f};
            #pragma unroll
            for (int kt = 0; kt < KT; kt++) {
                int kof = kt * 16 + 2 * tg;
                u32 b0 = *reinterpret_cast<const u32*>(&hb[g][kof]);
                u32 b1 = *reinterpret_cast<const u32*>(&hb[g][kof + 8]);
                mma16816(d0, A[0][kt], b0, b1);
                mma16816(d1, A[1][kt], b0, b1);
            }
            // D -> gT transposed (n-major); GTP%32==12 -> conflict-free
            float (*gg)[GTP] = gT[grp];
            int n0 = 2 * tg;
            #pragma unroll
            for (int mi = 0; mi < 2; mi++) {
                const float* d = mi ? d1 : d0;
                int r_lo = (2 * lwid + mi) * 16 + g;
                int r_hi = r_lo + 8;
                if (r_lo < 200) { gg[n0][r_lo] = d[0]; gg[n0 + 1][r_lo] = d[1]; }
                if (r_hi < 200) { gg[n0][r_hi] = d[2]; gg[n0 + 1][r_hi] = d[3]; }
            }
        }
        NBAR(1 + grp);       // gates ready

        // ---- cell update: 2 cells/thread; h -> hT[grp][next] hi/lo bf16 ----
        if (upd) {
            const float (*gg)[GTP] = gT[grp];
            __nv_bfloat16 (*hw)[HTP] = hT[grp][(t + 1) & 1];
            #pragma unroll
            for (int m = 0; m < 2; m++) {
                int n = 2 * q + m;
                float xv = x_sm[grp][tt][n];
                float I = gg[n][j]          + fmaf(wxi, xv, bii);
                float F = gg[n][j + HH]     + fmaf(wxf, xv, bif);
                float G = gg[n][j + 2*HH]   + fmaf(wxg, xv, big);
                float O = gg[n][j + 3*HH]   + fmaf(wxo, xv, bio);
                cc[m] = sigap(F) * cc[m] + sigap(I) * tanhap(G);
                hh[m] = sigap(O) * tanhap(cc[m]);
                __nv_bfloat16 hi = __float2bfloat16(hh[m]);
                float lo = hh[m] - __bfloat162float(hi);
                hw[n][j]          = hi;
                hw[n][j + HH]     = __float2bfloat16(lo);
                hw[n][j + 2 * HH] = hi;
            }
        }
        NBAR(1 + grp);       // hT[next] ready; gT free
    }

    // ================= FC epilogue on h_T =================
    if (upd) {
        #pragma unroll
        for (int m = 0; m < 2; m++) gT[grp][2 * q + m][j] = hh[m];
    }
    NBAR(1 + grp);
    if (ltid < NG * 3) {
        int bb = ltid / 3, o = ltid % 3;
        float s = fc_b[o];
        #pragma unroll
        for (int k = 0; k < HH; k++) s += gT[grp][bb][k] * fc_w[o * HH + k];
        out[(size_t)(b0g + bb) * 3 + o] = s;
    }
}

extern "C" void kernel_launch(void* const* d_in, const int* in_sizes, int n_in,
                              void* d_out, int out_size) {
    const float* x    = (const float*)d_in[0];
    const float* W_ih = (const float*)d_in[1];
    const float* W_hh = (const float*)d_in[2];
    const float* b_ih = (const float*)d_in[3];
    const float* b_hh = (const float*)d_in[4];
    const float* fc_w = (const float*)d_in[5];
    const float* fc_b = (const float*)d_in[6];
    lstm_mma<<<2048 / NBAT, NTH>>>(x, W_ih, W_hh, b_ih, b_hh, fc_w, fc_b, (float*)d_out);
}

// round 15
// speedup vs baseline: 2.2548x; 1.5635x over previous
#include <cuda_runtime.h>
#include <cuda_fp16.h>

#define TT   512
#define HH   50
#define NTH  448         // 2 groups x 224 (7 warps each)
#define NBAT 16          // per block; 8 per group
#define NG   8           // batches per group
#define KT   7           // k16 tiles: K=112 = [Whi_fp16(50) | Wlo_fp16(50) | pad(12)]
#define HTP  120         // fp16 per hT row (240B = 60 words -> conflict-free B loads)

typedef unsigned int u32;

__device__ __forceinline__ float tanhap(float x) {
    float y; asm("tanh.approx.f32 %0, %1;" : "=f"(y) : "f"(x)); return y;
}
__device__ __forceinline__ float sigap(float x) {
    return fmaf(tanhap(0.5f * x), 0.5f, 0.5f);
}
__device__ __forceinline__ u32 pkhf(float a, float b) {
    u32 lo = (u32)__half_as_ushort(__float2half_rn(a));
    u32 hi = (u32)__half_as_ushort(__float2half_rn(b));
    return (hi << 16) | lo;
}
__device__ __forceinline__ void mma16816(float* d, const u32* a, u32 b0, u32 b1) {
    asm volatile(
        "mma.sync.aligned.m16n8k16.row.col.f32.f16.f16.f32 "
        "{%0,%1,%2,%3}, {%4,%5,%6,%7}, {%8,%9}, {%0,%1,%2,%3};"
        : "+f"(d[0]), "+f"(d[1]), "+f"(d[2]), "+f"(d[3])
        : "r"(a[0]), "r"(a[1]), "r"(a[2]), "r"(a[3]), "r"(b0), "r"(b1));
}

#define NBAR(id) asm volatile("bar.sync %0, 224;" :: "r"(id) : "memory")

// Permuted A element. mma row r (0..223) maps to gate s = (r%32)/8 of unit
// j = 8*(r/32) + (r%8). k<50: fp16 hi of W[s*50+j][k]; 50..99: fp16 lo
// residual; else 0. Units j>=50 zero.
__device__ __forceinline__ float wperm(const float* W, int r, int k, int part) {
    int w = r >> 5, s = (r & 31) >> 3, g = r & 7;
    int j = 8 * w + g;
    if (j >= HH || k >= 2 * HH) return 0.f;
    int kk = (k < HH) ? k : k - HH;
    float v = W[(s * HH + j) * HH + kk];
    float hi = __half2float(__float2half_rn(v));
    return (k < HH) ? v : (v - hi);     // hi part rounds in pkhf; lo is residual
}

__global__ void __launch_bounds__(NTH, 1)
lstm_mma(const float* __restrict__ x,    const float* __restrict__ W_ih,
         const float* __restrict__ W_hh, const float* __restrict__ b_ih,
         const float* __restrict__ b_hh, const float* __restrict__ fc_w,
         const float* __restrict__ fc_b, float* __restrict__ out)
{
    // hT[grp][buf][n][k]: B operand (fp16, k-major, double buffered)
    __shared__ __align__(16) __half hT[2][2][NG][HTP];   // 7.7 KB
    __shared__ __align__(16) float x_sm[2][64][NG];      // 4 KB chunked x
    __shared__ __align__(16) float fcb[2][NG][HH + 2];   // fp32 h_T staging
    __shared__ float sink;

    const int tid  = threadIdx.x;
    const int grp  = (tid < 224) ? 0 : 1;
    const int ltid = tid - grp * 224;
    const int lwid = ltid >> 5;          // 0..6
    const int lan  = ltid & 31;
    const int g    = lan >> 2;
    const int tg   = lan & 3;
    const int b0g  = (int)blockIdx.x * NBAT + grp * NG;

    // this thread's unit and batch columns
    const int j  = 8 * lwid + g;         // 0..55; active if < 50
    const int n0 = 2 * tg;               // cols n0, n0+1
    const bool cell = (j < HH);

    // ---- zero hT (h=0 at t=0; pad region stays 0 forever) ----
    for (int i = tid; i < 2 * 2 * NG * HTP / 2; i += NTH)
        reinterpret_cast<u32*>(&hT[0][0][0][0])[i] = 0;

    // ---- A fragments (fp16, W-rows permuted), persistent in registers ----
    u32 A[2][KT][4];
    #pragma unroll
    for (int mi = 0; mi < 2; mi++) {
        int r_lo = (2 * lwid + mi) * 16 + g;
        #pragma unroll
        for (int kt = 0; kt < KT; kt++) {
            int ka = kt * 16 + 2 * tg;
            A[mi][kt][0] = pkhf(wperm(W_hh, r_lo,     ka, 0), wperm(W_hh, r_lo,     ka + 1, 0));
            A[mi][kt][1] = pkhf(wperm(W_hh, r_lo + 8, ka, 0), wperm(W_hh, r_lo + 8, ka + 1, 0));
            A[mi][kt][2] = pkhf(wperm(W_hh, r_lo,     ka + 8, 0), wperm(W_hh, r_lo,     ka + 9, 0));
            A[mi][kt][3] = pkhf(wperm(W_hh, r_lo + 8, ka + 8, 0), wperm(W_hh, r_lo + 8, ka + 9, 0));
        }
    }

    // ---- per-thread update constants for unit j ----
    float wxi = 0.f, wxf = 0.f, wxg = 0.f, wxo = 0.f;
    float bii = 0.f, bif = 0.f, big = 0.f, bio = 0.f;
    if (cell) {
        wxi = W_ih[j];          bii = b_ih[j]          + b_hh[j];
        wxf = W_ih[j + HH];     bif = b_ih[j + HH]     + b_hh[j + HH];
        wxg = W_ih[j + 2*HH];   big = b_ih[j + 2*HH]   + b_hh[j + 2*HH];
        wxo = W_ih[j + 3*HH];   bio = b_ih[j + 3*HH]   + b_hh[j + 3*HH];
    }
    float cc[2] = {0.f, 0.f}, hh[2] = {0.f, 0.f};

    __syncthreads();   // shared init done before groups diverge

    // ---- anti-phase stagger for group 1 (~half step) ----
    if (grp == 1) {
        float d = b_hh[0];
        #pragma unroll 1
        for (int i = 0; i < 80; i++) d = fmaf(d, 1.0000001f, 1e-7f);
        if (d == -1e30f) sink = d;   // never true; defeats DCE
    }

    // ================= recurrence =================
    #pragma unroll 1
    for (int t = 0; t < TT; t++) {
        const int tt = t & 63;
        if (tt == 0) {
            // refill x chunk: 8 batches x 16 float4 = 128 loads
            if (ltid < 128) {
                int bb = ltid >> 4, qq = ltid & 15;
                float4 v = reinterpret_cast<const float4*>(x)
                               [(size_t)(b0g + bb) * 128 + (t >> 6) * 16 + qq];
                x_sm[grp][qq * 4 + 0][bb] = v.x; x_sm[grp][qq * 4 + 1][bb] = v.y;
                x_sm[grp][qq * 4 + 2][bb] = v.z; x_sm[grp][qq * 4 + 3][bb] = v.w;
            }
            NBAR(1 + grp);
        }

        // ---- GEMM: D[224x8] = A @ hT[grp][t&1]; gates land in-thread ----
        float d0[4] = {0.f, 0.f, 0.f, 0.f};   // (i n0, i n1, f n0, f n1)
        float d1[4] = {0.f, 0.f, 0.f, 0.f};   // (g n0, g n1, o n0, o n1)
        {
            const __half (*hb)[HTP] = hT[grp][t & 1];
            #pragma unroll
            for (int kt = 0; kt < KT; kt++) {
                int kof = kt * 16 + 2 * tg;
                u32 b0 = *reinterpret_cast<const u32*>(&hb[g][kof]);
                u32 b1 = *reinterpret_cast<const u32*>(&hb[g][kof + 8]);
                mma16816(d0, A[0][kt], b0, b1);
                mma16816(d1, A[1][kt], b0, b1);
            }
        }

        // ---- in-register cell update; write h (fp16) into hT[next] ----
        if (cell) {
            __half (*hw)[HTP] = hT[grp][(t + 1) & 1];
            float xv0 = x_sm[grp][tt][n0], xv1 = x_sm[grp][tt][n0 + 1];

            float I0 = d0[0] + fmaf(wxi, xv0, bii), I1 = d0[1] + fmaf(wxi, xv1, bii);
            float F0 = d0[2] + fmaf(wxf, xv0, bif), F1 = d0[3] + fmaf(wxf, xv1, bif);
            float G0 = d1[0] + fmaf(wxg, xv0, big), G1 = d1[1] + fmaf(wxg, xv1, big);
            float O0 = d1[2] + fmaf(wxo, xv0, bio), O1 = d1[3] + fmaf(wxo, xv1, bio);

            cc[0] = sigap(F0) * cc[0] + sigap(I0) * tanhap(G0);
            cc[1] = sigap(F1) * cc[1] + sigap(I1) * tanhap(G1);
            hh[0] = sigap(O0) * tanhap(cc[0]);
            hh[1] = sigap(O1) * tanhap(cc[1]);

            __half h0 = __float2half_rn(hh[0]);
            __half h1 = __float2half_rn(hh[1]);
            hw[n0][j]          = h0;   hw[n0][j + HH]     = h0;
            hw[n0 + 1][j]      = h1;   hw[n0 + 1][j + HH] = h1;
        }
        NBAR(1 + grp);       // hT[next] complete
    }

    // ================= FC epilogue on exact fp32 h_T =================
    if (cell) {
        fcb[grp][n0][j]     = hh[0];
        fcb[grp][n0 + 1][j] = hh[1];
    }
    NBAR(1 + grp);
    if (ltid < NG * 3) {
        int bb = ltid / 3, o = ltid % 3;
        float s = fc_b[o];
        #pragma unroll
        for (int k = 0; k < HH; k++) s += fcb[grp][bb][k] * fc_w[o * HH + k];
        out[(size_t)(b0g + bb) * 3 + o] = s;
    }
}

extern "C" void kernel_launch(void* const* d_in, const int* in_sizes, int n_in,
                              void* d_out, int out_size) {
    const float* x    = (const float*)d_in[0];
    const float* W_ih = (const float*)d_in[1];
    const float* W_hh = (const float*)d_in[2];
    const float* b_ih = (const float*)d_in[3];
    const float* b_hh = (const float*)d_in[4];
    const float* fc_w = (const float*)d_in[5];
    const float* fc_b = (const float*)d_in[6];
    lstm_mma<<<2048 / NBAT, NTH>>>(x, W_ih, W_hh, b_ih, b_hh, fc_w, fc_b, (float*)d_out);
}

// round 16
// speedup vs baseline: 3.3817x; 1.4998x over previous
#include <cuda_runtime.h>
#include <cuda_fp16.h>

#define TT   512
#define HH   50
#define NTH  448         // 2 groups x 224 (7 warps each)
#define NBAT 14          // per block; 7 per group
#define NG   7           // real batches per group (8th column = masked garbage)
#define KT   4           // k16 tiles: K=64 = [W_fp16(50) | pad(14)]
#define HTP  72          // fp16 per hT row (36 words -> all-distinct banks)

typedef unsigned int u32;

__device__ __forceinline__ float tanhap(float x) {
    float y; asm("tanh.approx.f32 %0, %1;" : "=f"(y) : "f"(x)); return y;
}
__device__ __forceinline__ float sigap(float x) {
    return fmaf(tanhap(0.5f * x), 0.5f, 0.5f);
}
__device__ __forceinline__ u32 pkhf(float a, float b) {
    u32 lo = (u32)__half_as_ushort(__float2half_rn(a));
    u32 hi = (u32)__half_as_ushort(__float2half_rn(b));
    return (hi << 16) | lo;
}
__device__ __forceinline__ void mma16816(float* d, const u32* a, u32 b0, u32 b1) {
    asm volatile(
        "mma.sync.aligned.m16n8k16.row.col.f32.f16.f16.f32 "
        "{%0,%1,%2,%3}, {%4,%5,%6,%7}, {%8,%9}, {%0,%1,%2,%3};"
        : "+f"(d[0]), "+f"(d[1]), "+f"(d[2]), "+f"(d[3])
        : "r"(a[0]), "r"(a[1]), "r"(a[2]), "r"(a[3]), "r"(b0), "r"(b1));
}

#define NBAR(id) asm volatile("bar.sync %0, 224;" :: "r"(id) : "memory")

// Permuted A element (fp16 W, no residual). mma row r -> gate s=(r%32)/8 of
// unit j = 8*(r/32) + (r%8); k<50 -> W[(s*50+j)*50+k], else 0.
__device__ __forceinline__ float wperm(const float* W, int r, int k) {
    int w = r >> 5, s = (r & 31) >> 3, g = r & 7;
    int j = 8 * w + g;
    if (j >= HH || k >= HH) return 0.f;
    return W[(s * HH + j) * HH + k];
}

__global__ void __launch_bounds__(NTH, 1)
lstm_mma(const float* __restrict__ x,    const float* __restrict__ W_ih,
         const float* __restrict__ W_hh, const float* __restrict__ b_ih,
         const float* __restrict__ b_hh, const float* __restrict__ fc_w,
         const float* __restrict__ fc_b, float* __restrict__ out)
{
    // hT[grp][buf][n][k]: B operand (fp16, k-major, double buffered). 8 rows
    // allocated; row 7 is the garbage batch (bounded, never output).
    __shared__ __align__(16) __half hT[2][2][8][HTP];    // 4.6 KB
    __shared__ __align__(16) float x_sm[2][64][8];       // 4 KB chunked x
    __shared__ __align__(16) float fcb[2][8][HH + 2];    // fp32 h_T staging
    __shared__ float sink;

    const int tid  = threadIdx.x;
    const int grp  = (tid < 224) ? 0 : 1;
    const int ltid = tid - grp * 224;
    const int lwid = ltid >> 5;          // 0..6
    const int lan  = ltid & 31;
    const int g    = lan >> 2;
    const int tg   = lan & 3;
    const int b0g  = min((int)blockIdx.x * NBAT, 2048 - NBAT) + grp * NG;

    // this thread's unit and batch columns
    const int j  = 8 * lwid + g;         // 0..55; active if < 50
    const int n0 = 2 * tg;               // cols n0, n0+1
    const bool cell = (j < HH);

    // ---- zero hT (h=0 at t=0; pad cols 50..71 stay 0 forever) ----
    for (int i = tid; i < 2 * 2 * 8 * HTP / 2; i += NTH)
        reinterpret_cast<u32*>(&hT[0][0][0][0])[i] = 0;

    // ---- A fragments (fp16, W-rows permuted), persistent in registers ----
    u32 A[2][KT][4];
    #pragma unroll
    for (int mi = 0; mi < 2; mi++) {
        int r_lo = (2 * lwid + mi) * 16 + g;
        #pragma unroll
        for (int kt = 0; kt < KT; kt++) {
            int ka = kt * 16 + 2 * tg;
            A[mi][kt][0] = pkhf(wperm(W_hh, r_lo,     ka),     wperm(W_hh, r_lo,     ka + 1));
            A[mi][kt][1] = pkhf(wperm(W_hh, r_lo + 8, ka),     wperm(W_hh, r_lo + 8, ka + 1));
            A[mi][kt][2] = pkhf(wperm(W_hh, r_lo,     ka + 8), wperm(W_hh, r_lo,     ka + 9));
            A[mi][kt][3] = pkhf(wperm(W_hh, r_lo + 8, ka + 8), wperm(W_hh, r_lo + 8, ka + 9));
        }
    }

    // ---- per-thread update constants for unit j ----
    float wxi = 0.f, wxf = 0.f, wxg = 0.f, wxo = 0.f;
    float bii = 0.f, bif = 0.f, big = 0.f, bio = 0.f;
    if (cell) {
        wxi = W_ih[j];          bii = b_ih[j]          + b_hh[j];
        wxf = W_ih[j + HH];     bif = b_ih[j + HH]     + b_hh[j + HH];
        wxg = W_ih[j + 2*HH];   big = b_ih[j + 2*HH]   + b_hh[j + 2*HH];
        wxo = W_ih[j + 3*HH];   bio = b_ih[j + 3*HH]   + b_hh[j + 3*HH];
    }
    float cc[2] = {0.f, 0.f}, hh[2] = {0.f, 0.f};

    __syncthreads();   // shared init done before groups diverge

    // ---- anti-phase stagger for group 1 (~half step) ----
    if (grp == 1) {
        float d = b_hh[0];
        #pragma unroll 1
        for (int i = 0; i < 80; i++) d = fmaf(d, 1.0000001f, 1e-7f);
        if (d == -1e30f) sink = d;   // never true; defeats DCE
    }

    // ================= recurrence =================
    #pragma unroll 1
    for (int t = 0; t < TT; t++) {
        const int tt = t & 63;
        if (tt == 0) {
            // refill x chunk: 7 batches x 16 float4 = 112 loads
            if (ltid < NG * 16) {
                int bb = ltid >> 4, qq = ltid & 15;
                float4 v = reinterpret_cast<const float4*>(x)
                               [(size_t)(b0g + bb) * 128 + (t >> 6) * 16 + qq];
                x_sm[grp][qq * 4 + 0][bb] = v.x; x_sm[grp][qq * 4 + 1][bb] = v.y;
                x_sm[grp][qq * 4 + 2][bb] = v.z; x_sm[grp][qq * 4 + 3][bb] = v.w;
            }
            NBAR(1 + grp);
        }

        // ---- GEMM: D[224x8] = A @ hT[grp][t&1]; gates land in-thread ----
        float d0[4] = {0.f, 0.f, 0.f, 0.f};   // (i n0, i n1, f n0, f n1)
        float d1[4] = {0.f, 0.f, 0.f, 0.f};   // (g n0, g n1, o n0, o n1)
        {
            const __half (*hb)[HTP] = hT[grp][t & 1];
            #pragma unroll
            for (int kt = 0; kt < KT; kt++) {
                int kof = kt * 16 + 2 * tg;
                u32 b0 = *reinterpret_cast<const u32*>(&hb[g][kof]);
                u32 b1 = *reinterpret_cast<const u32*>(&hb[g][kof + 8]);
                mma16816(d0, A[0][kt], b0, b1);
                mma16816(d1, A[1][kt], b0, b1);
            }
        }

        // ---- in-register cell update; write h (fp16) into hT[next] ----
        if (cell) {
            __half (*hw)[HTP] = hT[grp][(t + 1) & 1];
            float xv0 = x_sm[grp][tt][n0], xv1 = x_sm[grp][tt][n0 + 1];

            float I0 = d0[0] + fmaf(wxi, xv0, bii), I1 = d0[1] + fmaf(wxi, xv1, bii);
            float F0 = d0[2] + fmaf(wxf, xv0, bif), F1 = d0[3] + fmaf(wxf, xv1, bif);
            float G0 = d1[0] + fmaf(wxg, xv0, big), G1 = d1[1] + fmaf(wxg, xv1, big);
            float O0 = d1[2] + fmaf(wxo, xv0, bio), O1 = d1[3] + fmaf(wxo, xv1, bio);

            cc[0] = sigap(F0) * cc[0] + sigap(I0) * tanhap(G0);
            cc[1] = sigap(F1) * cc[1] + sigap(I1) * tanhap(G1);
            hh[0] = sigap(O0) * tanhap(cc[0]);
            hh[1] = sigap(O1) * tanhap(cc[1]);

            hw[n0][j]     = __float2half_rn(hh[0]);
            hw[n0 + 1][j] = __float2half_rn(hh[1]);
        }
        NBAR(1 + grp);       // hT[next] complete
    }

    // ================= FC epilogue on exact fp32 h_T =================
    if (cell) {
        fcb[grp][n0][j]     = hh[0];
        fcb[grp][n0 + 1][j] = hh[1];
    }
    NBAR(1 + grp);
    if (ltid < NG * 3) {
        int bb = ltid / 3, o = ltid % 3;
        float s = fc_b[o];
        #pragma unroll
        for (int k = 0; k < HH; k++) s += fcb[grp][bb][k] * fc_w[o * HH + k];
        out[(size_t)(b0g + bb) * 3 + o] = s;
    }
}

extern "C" void kernel_launch(void* const* d_in, const int* in_sizes, int n_in,
                              void* d_out, int out_size) {
    const float* x    = (const float*)d_in[0];
    const float* W_ih = (const float*)d_in[1];
    const float* W_hh = (const float*)d_in[2];
    const float* b_ih = (const float*)d_in[3];
    const float* b_hh = (const float*)d_in[4];
    const float* fc_w = (const float*)d_in[5];
    const float* fc_b = (const float*)d_in[6];
    lstm_mma<<<147, NTH>>>(x, W_ih, W_hh, b_ih, b_hh, fc_w, fc_b, (float*)d_out);
}